// round 1
// baseline (speedup 1.0000x reference)
#include <cuda_runtime.h>
#include <cstdint>

#define NB   256
#define TT   300
#define NV   25
#define NCH  75
#define HID  64
#define TP   60
#define WS   68   // transposed-weight row stride (floats)
#define HS   65   // h row stride (floats)

// parent joint (0-indexed) from ntu_pairs
__constant__ int c_par[NV] = {1,20,20,2,20,4,5,6,20,8,9,10,0,12,13,14,0,16,17,18,20,22,7,24,11};

// folded BN affine per channel (index = c*25+v), per branch
__device__ float g_sc1[NCH], g_sh1[NCH], g_sc2[NCH], g_sh2[NCH];

typedef unsigned long long u64;

__device__ __forceinline__ u64 pk2(float a, float b){
    u64 r; asm("mov.b64 %0,{%1,%2};" : "=l"(r) : "f"(a), "f"(b)); return r;
}
__device__ __forceinline__ void upk2(u64 a, float& x, float& y){
    asm("mov.b64 {%0,%1},%2;" : "=f"(x), "=f"(y) : "l"(a));
}
__device__ __forceinline__ u64 fma2(u64 a, u64 b, u64 c){
    u64 d; asm("fma.rn.f32x2 %0,%1,%2,%3;" : "=l"(d) : "l"(a), "l"(b), "l"(c)); return d;
}

// ---------------------------------------------------------------------------
// Pass 1: per-channel batch stats for bone and t_bone, folded with BN affine.
// grid = 25 blocks (one per joint v), 256 threads (one per batch index n).
// ---------------------------------------------------------------------------
__global__ __launch_bounds__(NB) void stats_kernel(
    const float* __restrict__ x,
    const float* __restrict__ g1, const float* __restrict__ b1g,
    const float* __restrict__ g2, const float* __restrict__ b2g)
{
    int v  = blockIdx.x;
    int n  = threadIdx.x;
    int ci = v * 3, pi = c_par[v] * 3;
    const float* xr = x + (size_t)n * TT * NCH;

    float s1x=0,s1y=0,s1z=0, q1x=0,q1y=0,q1z=0;
    float s2x=0,s2y=0,s2z=0, q2x=0,q2y=0,q2z=0;
    float p0=0, p1=0, p2=0;
    for (int t = 0; t < TT; t++) {
        const float* r = xr + t * NCH;
        float b0 = r[ci+0] - r[pi+0];
        float b1 = r[ci+1] - r[pi+1];
        float b2 = r[ci+2] - r[pi+2];
        s1x += b0; q1x += b0*b0;
        s1y += b1; q1y += b1*b1;
        s1z += b2; q1z += b2*b2;
        if (t > 0) {
            float d0 = b0-p0, d1 = b1-p1, d2 = b2-p2;
            s2x += d0; q2x += d0*d0;
            s2y += d1; q2y += d1*d1;
            s2z += d2; q2z += d2*d2;
        }
        p0 = b0; p1 = b1; p2 = b2;
    }

    __shared__ float red[12][NB];
    red[0][n]=s1x; red[1][n]=s1y; red[2][n]=s1z;
    red[3][n]=q1x; red[4][n]=q1y; red[5][n]=q1z;
    red[6][n]=s2x; red[7][n]=s2y; red[8][n]=s2z;
    red[9][n]=q2x; red[10][n]=q2y; red[11][n]=q2z;
    __syncthreads();
    for (int s = NB/2; s > 0; s >>= 1) {
        if (n < s) {
            #pragma unroll
            for (int j = 0; j < 12; j++) red[j][n] += red[j][n+s];
        }
        __syncthreads();
    }
    if (n == 0) {
        const float inv = 1.0f / (float)(NB * TT);   // t_bone pad-zeros count too
        #pragma unroll
        for (int c = 0; c < 3; c++) {
            int ch = c * NV + v;                      // BN channel order: c*V + v
            float m1 = red[c][0] * inv;
            float var1 = red[3+c][0] * inv - m1 * m1;
            float sc1 = rsqrtf(var1 + 1e-5f) * g1[ch];
            g_sc1[ch] = sc1;
            g_sh1[ch] = b1g[ch] - m1 * sc1;
            float m2 = red[6+c][0] * inv;
            float var2 = red[9+c][0] * inv - m2 * m2;
            float sc2 = rsqrtf(var2 + 1e-5f) * g2[ch];
            g_sc2[ch] = sc2;
            g_sh2[ch] = b2g[ch] - m2 * sc2;
        }
    }
}

// ---------------------------------------------------------------------------
// Pass 2: fused bone/t_bone -> folded-BN -> layer1 -> relu -> layer2 -> relu -> sum
// grid (5 t-tiles, 25 v, 32 n-groups); each block loops 8 batch indices.
// ---------------------------------------------------------------------------
extern __shared__ float smem[];

__global__ __launch_bounds__(256, 3) void main_kernel(
    const float* __restrict__ x,
    const float* __restrict__ w1a, const float* __restrict__ b1a,
    const float* __restrict__ w1b, const float* __restrict__ b1b,
    const float* __restrict__ w2a, const float* __restrict__ b2a,
    const float* __restrict__ w2b, const float* __restrict__ b2b,
    float* __restrict__ out)
{
    float* wt1 = smem;                     // [HID][WS]  transposed: wt[k][o]
    float* wt2 = wt1 + HID * WS;
    float* h1s = wt2 + HID * WS;           // [HID][HS]  h[k][pt], pts padded to 64
    float* h2s = h1s + HID * HS;
    float* bsh = h2s + HID * HS;           // [3][TP+1]

    const int tid = threadIdx.x;
    const int v   = blockIdx.y;
    const int t0  = blockIdx.x * TP;

    // one-time transposed-weight staging (amortized over 8 batches)
    for (int i = tid; i < HID * HID; i += 256) {
        int o = i >> 6, h = i & 63;
        wt1[h * WS + o] = w1b[i];
        wt2[h * WS + o] = w2b[i];
    }

    // ---- layer-1 folded params (per thread: one output channel o1) ----
    const int o1  = tid & 63;
    const int grp = tid >> 6;        // 0..3
    float sc10 = g_sc1[v], sc11 = g_sc1[NV+v], sc12 = g_sc1[2*NV+v];
    float sh10 = g_sh1[v], sh11 = g_sh1[NV+v], sh12 = g_sh1[2*NV+v];
    float sc20 = g_sc2[v], sc21 = g_sc2[NV+v], sc22 = g_sc2[2*NV+v];
    float sh20 = g_sh2[v], sh21 = g_sh2[NV+v], sh22 = g_sh2[2*NV+v];
    float wa0 = w1a[o1*3+0], wa1 = w1a[o1*3+1], wa2 = w1a[o1*3+2];
    float ew10 = wa0*sc10, ew11 = wa1*sc11, ew12 = wa2*sc12;
    float eb1  = b1a[o1] + wa0*sh10 + wa1*sh11 + wa2*sh12;
    float wc0 = w2a[o1*3+0], wc1 = w2a[o1*3+1], wc2 = w2a[o1*3+2];
    float ew20 = wc0*sc20, ew21 = wc1*sc21, ew22 = wc2*sc22;
    float eb2  = b2a[o1] + wc0*sh20 + wc1*sh21 + wc2*sh22;

    const int ci = v * 3, pi = c_par[v] * 3;
    const int to = tid >> 5;         // 0..7 : owns o = to*8 .. to*8+7
    const int tp = tid & 31;         // points tp and tp+32

    for (int ni = 0; ni < 8; ni++) {
        const int n = blockIdx.z * 8 + ni;
        __syncthreads();   // previous phase-2 reads done before rewriting bsh/h

        // stage bone for this (n, v, t-tile); one extra frame for t-diff
        if (tid < 3 * (TP + 1)) {
            int c = tid / (TP + 1), tt = tid - c * (TP + 1);
            int t = t0 + tt;
            float bv = 0.0f;
            if (t < TT) {
                const float* r = x + ((size_t)n * TT + t) * NCH;
                bv = r[ci + c] - r[pi + c];
            }
            bsh[c * (TP + 1) + tt] = bv;
        }
        __syncthreads();

        // phase 1: h1/h2 for 60 points (each thread: fixed o1, strided pts)
        for (int pt = grp; pt < TP; pt += 4) {
            float b0 = bsh[pt], b1 = bsh[(TP+1) + pt], b2 = bsh[2*(TP+1) + pt];
            float h1 = fmaf(ew10, b0, fmaf(ew11, b1, fmaf(ew12, b2, eb1)));
            h1 = fmaxf(h1, 0.0f);
            float d0, d1, d2;
            int t = t0 + pt;
            if (t < TT - 1) {
                d0 = bsh[pt+1] - b0;
                d1 = bsh[(TP+1) + pt+1] - b1;
                d2 = bsh[2*(TP+1) + pt+1] - b2;
            } else { d0 = d1 = d2 = 0.0f; }
            float h2 = fmaf(ew20, d0, fmaf(ew21, d1, fmaf(ew22, d2, eb2)));
            h2 = fmaxf(h2, 0.0f);
            h1s[o1 * HS + pt] = h1;
            h2s[o1 * HS + pt] = h2;
        }
        // zero-pad points 60..63 so the k-loop needs no guards
        h1s[o1 * HS + TP + grp] = 0.0f;
        h2s[o1 * HS + TP + grp] = 0.0f;
        __syncthreads();

        // phase 2: out[64, 64pts] = W1b @ H1 (+bias,relu) + W2b @ H2 (+bias,relu)
        // packed f32x2 FMAs: pairs over adjacent o, broadcast h.
        u64 a1[4][2], a2[4][2];
        #pragma unroll
        for (int i = 0; i < 4; i++) { a1[i][0]=0ull; a1[i][1]=0ull; a2[i][0]=0ull; a2[i][1]=0ull; }

        #pragma unroll 8
        for (int k = 0; k < HID; k++) {
            const float* w1p = wt1 + k * WS + to * 8;
            const float* w2p = wt2 + k * WS + to * 8;
            ulonglong2 wA = *(const ulonglong2*)(w1p);      // o pairs (0,1),(2,3)
            ulonglong2 wB = *(const ulonglong2*)(w1p + 4);  // o pairs (4,5),(6,7)
            ulonglong2 wC = *(const ulonglong2*)(w2p);
            ulonglong2 wD = *(const ulonglong2*)(w2p + 4);
            float hv0 = h1s[k * HS + tp], hv1 = h1s[k * HS + tp + 32];
            float gv0 = h2s[k * HS + tp], gv1 = h2s[k * HS + tp + 32];
            u64 hh0 = pk2(hv0, hv0), hh1 = pk2(hv1, hv1);
            u64 gg0 = pk2(gv0, gv0), gg1 = pk2(gv1, gv1);
            a1[0][0] = fma2(wA.x, hh0, a1[0][0]);  a1[0][1] = fma2(wA.x, hh1, a1[0][1]);
            a1[1][0] = fma2(wA.y, hh0, a1[1][0]);  a1[1][1] = fma2(wA.y, hh1, a1[1][1]);
            a1[2][0] = fma2(wB.x, hh0, a1[2][0]);  a1[2][1] = fma2(wB.x, hh1, a1[2][1]);
            a1[3][0] = fma2(wB.y, hh0, a1[3][0]);  a1[3][1] = fma2(wB.y, hh1, a1[3][1]);
            a2[0][0] = fma2(wC.x, gg0, a2[0][0]);  a2[0][1] = fma2(wC.x, gg1, a2[0][1]);
            a2[1][0] = fma2(wC.y, gg0, a2[1][0]);  a2[1][1] = fma2(wC.y, gg1, a2[1][1]);
            a2[2][0] = fma2(wD.x, gg0, a2[2][0]);  a2[2][1] = fma2(wD.x, gg1, a2[2][1]);
            a2[3][0] = fma2(wD.y, gg0, a2[3][0]);  a2[3][1] = fma2(wD.y, gg1, a2[3][1]);
        }

        // epilogue: bias + relu + sum, write out[n][o][v][t]
        const size_t base = (size_t)n * (HID * NV * TT) + (size_t)v * TT + (t0 + tp);
        #pragma unroll
        for (int i = 0; i < 4; i++) {
            int oe = to * 8 + 2 * i;
            float bb0 = b1b[oe], bb1 = b1b[oe + 1];
            float cb0 = b2b[oe], cb1 = b2b[oe + 1];
            float x0, x1, y0, y1;
            upk2(a1[i][0], x0, x1);
            upk2(a2[i][0], y0, y1);
            out[base + (size_t)oe * (NV * TT)]       = fmaxf(x0 + bb0, 0.f) + fmaxf(y0 + cb0, 0.f);
            out[base + (size_t)(oe + 1) * (NV * TT)] = fmaxf(x1 + bb1, 0.f) + fmaxf(y1 + cb1, 0.f);
            if (tp < TP - 32) {   // second point tp+32 valid only below 60
                upk2(a1[i][1], x0, x1);
                upk2(a2[i][1], y0, y1);
                out[base + 32 + (size_t)oe * (NV * TT)]       = fmaxf(x0 + bb0, 0.f) + fmaxf(y0 + cb0, 0.f);
                out[base + 32 + (size_t)(oe + 1) * (NV * TT)] = fmaxf(x1 + bb1, 0.f) + fmaxf(y1 + cb1, 0.f);
            }
        }
    }
}

extern "C" void kernel_launch(void* const* d_in, const int* in_sizes, int n_in,
                              void* d_out, int out_size)
{
    const float* x    = (const float*)d_in[0];
    const float* g1   = (const float*)d_in[1];
    const float* b1g  = (const float*)d_in[2];
    const float* w1a  = (const float*)d_in[3];
    const float* b1a  = (const float*)d_in[4];
    const float* w1b  = (const float*)d_in[5];
    const float* b1b  = (const float*)d_in[6];
    const float* g2   = (const float*)d_in[7];
    const float* b2g  = (const float*)d_in[8];
    const float* w2a  = (const float*)d_in[9];
    const float* b2a  = (const float*)d_in[10];
    const float* w2b  = (const float*)d_in[11];
    const float* b2b  = (const float*)d_in[12];
    float* out = (float*)d_out;

    stats_kernel<<<NV, NB>>>(x, g1, b1g, g2, b2g);

    const int smem_bytes = (2 * HID * WS + 2 * HID * HS + 3 * (TP + 1)) * sizeof(float);
    static int configured = 0;
    if (!configured) {
        cudaFuncSetAttribute(main_kernel, cudaFuncAttributeMaxDynamicSharedMemorySize, smem_bytes);
        configured = 1;
    }
    dim3 grid(TT / TP, NV, NB / 8);
    main_kernel<<<grid, 256, smem_bytes>>>(x, w1a, b1a, w1b, b1b,
                                           w2a, b2a, w2b, b2b, out);
}

// round 5
// speedup vs baseline: 2.0424x; 2.0424x over previous
#include <cuda_runtime.h>
#include <cuda_bf16.h>
#include <cstdint>

#define NN   256
#define TT   300
#define NV   25
#define NCH  75
#define NP   (NV * TT)            // 7500
#define MTILE 256                 // points per CTA tile
#define ITER  2                   // tiles per CTA
#define THREADS 512

// parent joint (0-indexed)
__constant__ int c_par[NV] = {1,20,20,2,20,4,5,6,20,8,9,10,0,12,13,14,0,16,17,18,20,22,7,24,11};

// folded BN affine per channel (index = c*25+v)
__device__ float g_sc1[NCH], g_sh1[NCH], g_sc2[NCH], g_sh2[NCH];

// bone / t_bone scratch: [n][ch 0..5][p]  (ch 0-2 bone xyz, 3-5 tbone xyz)
__device__ float g_bone[(size_t)NN * 6 * NP];

// stats partials
#define SBLK 1024
__device__ float g_ps1[NCH * 3 * SBLK];
__device__ float g_pq1[NCH * 3 * SBLK];
__device__ float g_ps2[NCH * 3 * SBLK];
__device__ float g_pq2[NCH * 3 * SBLK];

__device__ __forceinline__ uint32_t s2u(const void* p) {
    uint32_t a;
    asm("{ .reg .u64 t; cvta.to.shared.u64 t, %1; cvt.u32.u64 %0, t; }" : "=r"(a) : "l"(p));
    return a;
}

__device__ __forceinline__ void ldsm4(uint32_t* r, uint32_t addr) {
    asm volatile("ldmatrix.sync.aligned.m8n8.x4.shared.b16 {%0,%1,%2,%3}, [%4];"
                 : "=r"(r[0]), "=r"(r[1]), "=r"(r[2]), "=r"(r[3]) : "r"(addr));
}

__device__ __forceinline__ void mma16816(float* d, const uint32_t* a, uint32_t b0, uint32_t b1) {
    asm volatile(
        "mma.sync.aligned.m16n8k16.row.col.f32.bf16.bf16.f32 "
        "{%0,%1,%2,%3}, {%4,%5,%6,%7}, {%8,%9}, {%0,%1,%2,%3};"
        : "+f"(d[0]), "+f"(d[1]), "+f"(d[2]), "+f"(d[3])
        : "r"(a[0]), "r"(a[1]), "r"(a[2]), "r"(a[3]), "r"(b0), "r"(b1));
}

// ---------------------------------------------------------------------------
// stats + bone precompute: grid (4 t-chunks, 256 n), 256 threads
// ---------------------------------------------------------------------------
__global__ __launch_bounds__(256) void stats1(const float* __restrict__ x) {
    __shared__ float rows[76][76];
    int tc = blockIdx.x, n = blockIdx.y;
    int t0 = tc * 75;
    int tid = threadIdx.x;

    for (int i = tid; i < 76 * NCH; i += 256) {
        int r = i / NCH, c = i - r * NCH;
        int t = t0 + r;
        rows[r][c] = (t < TT) ? x[((size_t)n * TT + t) * NCH + c] : 0.0f;
    }
    __syncthreads();

    // write bone / tbone planes, coalesced (r fastest)
    float* bp = g_bone + (size_t)n * 6 * NP;
    for (int i = tid; i < NCH * 75; i += 256) {
        int ch = i / 75, r = i - ch * 75;
        int c = ch / NV, v = ch - c * NV;
        int ci = v * 3 + c, pi = c_par[v] * 3 + c;
        float b = rows[r][ci] - rows[r][pi];
        float d = 0.0f;
        if (t0 + r < TT - 1) d = (rows[r + 1][ci] - rows[r + 1][pi]) - b;
        size_t pidx = (size_t)v * TT + t0 + r;
        bp[(size_t)c * NP + pidx]       = b;
        bp[(size_t)(3 + c) * NP + pidx] = d;
    }

    // stats partials (deterministic)
    int g = tid / NCH;
    int ch = tid - g * NCH;
    if (g < 3) {
        int c = ch / NV, v = ch - c * NV;
        int ci = v * 3 + c, pi = c_par[v] * 3 + c;
        float s1 = 0, q1 = 0, s2 = 0, q2 = 0;
        for (int r = g; r < 75; r += 3) {
            float b = rows[r][ci] - rows[r][pi];
            s1 += b; q1 += b * b;
            if (t0 + r < TT - 1) {
                float d = (rows[r + 1][ci] - rows[r + 1][pi]) - b;
                s2 += d; q2 += d * d;
            }
        }
        int idx = (ch * 3 + g) * SBLK + (tc * NN + n);
        g_ps1[idx] = s1; g_pq1[idx] = q1;
        g_ps2[idx] = s2; g_pq2[idx] = q2;
    }
}

__global__ __launch_bounds__(256) void stats2(
    const float* __restrict__ g1, const float* __restrict__ b1,
    const float* __restrict__ g2, const float* __restrict__ b2)
{
    int ch = blockIdx.x;
    int tid = threadIdx.x;
    float s1 = 0, q1 = 0, s2 = 0, q2 = 0;
    for (int g = 0; g < 3; g++) {
        int base = (ch * 3 + g) * SBLK;
        for (int i = tid; i < SBLK; i += 256) {
            s1 += g_ps1[base + i]; q1 += g_pq1[base + i];
            s2 += g_ps2[base + i]; q2 += g_pq2[base + i];
        }
    }
    __shared__ float red[4][256];
    red[0][tid] = s1; red[1][tid] = q1; red[2][tid] = s2; red[3][tid] = q2;
    __syncthreads();
    for (int s = 128; s > 0; s >>= 1) {
        if (tid < s) {
            #pragma unroll
            for (int j = 0; j < 4; j++) red[j][tid] += red[j][tid + s];
        }
        __syncthreads();
    }
    if (tid == 0) {
        const float inv = 1.0f / (float)(NN * TT);
        float m1 = red[0][0] * inv;
        float v1 = red[1][0] * inv - m1 * m1;
        float sc1 = rsqrtf(v1 + 1e-5f) * g1[ch];
        g_sc1[ch] = sc1;
        g_sh1[ch] = b1[ch] - m1 * sc1;
        float m2 = red[2][0] * inv;
        float v2 = red[3][0] * inv - m2 * m2;
        float sc2 = rsqrtf(v2 + 1e-5f) * g2[ch];
        g_sc2[ch] = sc2;
        g_sh2[ch] = b2[ch] - m2 * sc2;
    }
}

// ---------------------------------------------------------------------------
// main kernel
// smem layout (bytes):
#define ASTR 144                       // A row stride bytes (72 bf16)
#define BSTR 272                       // B row stride bytes (136 bf16)
#define OFF_A1H 0
#define OFF_A1L (OFF_A1H + MTILE * ASTR)
#define OFF_A2H (OFF_A1L + MTILE * ASTR)
#define OFF_A2L (OFF_A2H + MTILE * ASTR)
#define OFF_B1  (OFF_A2L + MTILE * ASTR)
#define OFF_B2  (OFF_B1 + 64 * BSTR)
#define OFF_WP1 (OFF_B2 + 64 * BSTR)
#define OFF_WP2 (OFF_WP1 + 1024)
#define OFF_BB1 (OFF_WP2 + 1024)
#define OFF_BB2 (OFF_BB1 + 256)
#define SMEM_SZ (OFF_BB2 + 256)

extern __shared__ char smem[];

__global__ __launch_bounds__(THREADS) void main_mma(
    const float* __restrict__ w1a, const float* __restrict__ b1a,
    const float* __restrict__ w1b, const float* __restrict__ b1b,
    const float* __restrict__ w2a, const float* __restrict__ b2a,
    const float* __restrict__ w2b, const float* __restrict__ b2b,
    float* __restrict__ out)
{
    const int tid  = threadIdx.x;
    const int wid  = tid >> 5, lane = tid & 31;
    const int n    = blockIdx.y;

    // ---- stage weights (hi/lo split), layer-1 tables, biases ----
    for (int i = tid; i < 64 * 64; i += THREADS) {
        int o = i >> 6, h = i & 63;
        float w = w1b[i];
        __nv_bfloat16 hi = __float2bfloat16_rn(w);
        __nv_bfloat16 lo = __float2bfloat16_rn(w - __bfloat162float(hi));
        *(__nv_bfloat16*)(smem + OFF_B1 + o * BSTR + h * 2)        = hi;
        *(__nv_bfloat16*)(smem + OFF_B1 + o * BSTR + 128 + h * 2)  = lo;
        w = w2b[i];
        hi = __float2bfloat16_rn(w);
        lo = __float2bfloat16_rn(w - __bfloat162float(hi));
        *(__nv_bfloat16*)(smem + OFF_B2 + o * BSTR + h * 2)        = hi;
        *(__nv_bfloat16*)(smem + OFF_B2 + o * BSTR + 128 + h * 2)  = lo;
    }
    if (tid < 64) {
        *(float4*)(smem + OFF_WP1 + tid * 16) =
            make_float4(w1a[tid * 3], w1a[tid * 3 + 1], w1a[tid * 3 + 2], b1a[tid]);
    } else if (tid < 128) {
        int o = tid - 64;
        *(float4*)(smem + OFF_WP2 + o * 16) =
            make_float4(w2a[o * 3], w2a[o * 3 + 1], w2a[o * 3 + 2], b2a[o]);
    } else if (tid < 192) {
        ((float*)(smem + OFF_BB1))[tid - 128] = b1b[tid - 128];
    } else if (tid < 256) {
        ((float*)(smem + OFF_BB2))[tid - 192] = b2b[tid - 192];
    }

    const int p    = tid & 255;        // local point (A row)
    const int half = tid >> 8;         // 0/1 : o-pair half
    const float* bnp = g_bone + (size_t)n * 6 * NP;

    // ldmatrix address components
    const uint32_t sA1h = s2u(smem + OFF_A1H), sA1l = s2u(smem + OFF_A1L);
    const uint32_t sA2h = s2u(smem + OFF_A2H), sA2l = s2u(smem + OFF_A2L);
    const uint32_t sB1  = s2u(smem + OFF_B1),  sB2  = s2u(smem + OFF_B2);
    const uint32_t aoff = (uint32_t)(wid * 16 + (lane & 15)) * ASTR + ((lane >> 4) * 8) * 2;
    const uint32_t boff = (uint32_t)(lane & 7) * BSTR + ((lane >> 3) & 1) * 16
                        + ((lane >> 4) & 1) * 128;

    for (int it = 0; it < ITER; it++) {
        const int tp0 = (blockIdx.x * ITER + it) * MTILE;
        // barrier every iteration: it=0 makes staging (WP/B/bias tables) visible
        // before the H phase reads them; it>0 protects A-smem rewrite vs prior MMA reads.
        __syncthreads();

        // ---- H phase: layer 1 (folded BN), hi/lo split into smem ----
        {
            const int pg  = tp0 + p;
            const int pgc = (pg < NP) ? pg : (NP - 1);
            const int v   = pgc / TT;
            float z0 = g_sc1[v]          * bnp[pgc]            + g_sh1[v];
            float z1 = g_sc1[NV + v]     * bnp[NP + pgc]       + g_sh1[NV + v];
            float z2 = g_sc1[2 * NV + v] * bnp[2 * NP + pgc]   + g_sh1[2 * NV + v];
            float y0 = g_sc2[v]          * bnp[3 * NP + pgc]   + g_sh2[v];
            float y1 = g_sc2[NV + v]     * bnp[4 * NP + pgc]   + g_sh2[NV + v];
            float y2 = g_sc2[2 * NV + v] * bnp[5 * NP + pgc]   + g_sh2[2 * NV + v];

            const uint32_t rowb = (uint32_t)p * ASTR;
            #pragma unroll
            for (int j = 0; j < 16; j++) {
                int oo = half * 16 + ((j + (lane >> 3)) & 15);
                int o0 = oo * 2;
                float4 wp = *(const float4*)(smem + OFF_WP1 + o0 * 16);
                float4 wq = *(const float4*)(smem + OFF_WP1 + (o0 + 1) * 16);
                float h0 = fmaxf(fmaf(wp.x, z0, fmaf(wp.y, z1, fmaf(wp.z, z2, wp.w))), 0.0f);
                float h1 = fmaxf(fmaf(wq.x, z0, fmaf(wq.y, z1, fmaf(wq.z, z2, wq.w))), 0.0f);
                uint32_t hi2, lo2;
                asm("cvt.rn.bf16x2.f32 %0, %1, %2;" : "=r"(hi2) : "f"(h1), "f"(h0));
                float e0 = __uint_as_float(hi2 << 16);
                float e1 = __uint_as_float(hi2 & 0xffff0000u);
                asm("cvt.rn.bf16x2.f32 %0, %1, %2;" : "=r"(lo2) : "f"(h1 - e1), "f"(h0 - e0));
                *(uint32_t*)(smem + OFF_A1H + rowb + oo * 4) = hi2;
                *(uint32_t*)(smem + OFF_A1L + rowb + oo * 4) = lo2;

                float4 vp = *(const float4*)(smem + OFF_WP2 + o0 * 16);
                float4 vq = *(const float4*)(smem + OFF_WP2 + (o0 + 1) * 16);
                float g0  = fmaxf(fmaf(vp.x, y0, fmaf(vp.y, y1, fmaf(vp.z, y2, vp.w))), 0.0f);
                float g1v = fmaxf(fmaf(vq.x, y0, fmaf(vq.y, y1, fmaf(vq.z, y2, vq.w))), 0.0f);
                asm("cvt.rn.bf16x2.f32 %0, %1, %2;" : "=r"(hi2) : "f"(g1v), "f"(g0));
                e0 = __uint_as_float(hi2 << 16);
                e1 = __uint_as_float(hi2 & 0xffff0000u);
                asm("cvt.rn.bf16x2.f32 %0, %1, %2;" : "=r"(lo2) : "f"(g1v - e1), "f"(g0 - e0));
                *(uint32_t*)(smem + OFF_A2H + rowb + oo * 4) = hi2;
                *(uint32_t*)(smem + OFF_A2L + rowb + oo * 4) = lo2;
            }
        }
        __syncthreads();

        // ---- MMA phase: out[16 rows x 64 cols] per warp, 3-pass bf16 split ----
        float a1[8][4], a2[8][4];
        #pragma unroll
        for (int ntt = 0; ntt < 8; ntt++)
            #pragma unroll
            for (int q = 0; q < 4; q++) { a1[ntt][q] = 0.f; a2[ntt][q] = 0.f; }

        #pragma unroll
        for (int kc = 0; kc < 4; kc++) {
            uint32_t A1h[4], A1l[4], A2h[4], A2l[4];
            ldsm4(A1h, sA1h + aoff + kc * 32);
            ldsm4(A1l, sA1l + aoff + kc * 32);
            ldsm4(A2h, sA2h + aoff + kc * 32);
            ldsm4(A2l, sA2l + aoff + kc * 32);
            #pragma unroll
            for (int nt = 0; nt < 8; nt++) {
                uint32_t b1[4], b2[4];
                ldsm4(b1, sB1 + boff + (uint32_t)nt * 8 * BSTR + kc * 32);
                ldsm4(b2, sB2 + boff + (uint32_t)nt * 8 * BSTR + kc * 32);
                mma16816(a1[nt], A1h, b1[0], b1[1]);   // hi*hi
                mma16816(a1[nt], A1l, b1[0], b1[1]);   // lo*hi
                mma16816(a1[nt], A1h, b1[2], b1[3]);   // hi*lo
                mma16816(a2[nt], A2h, b2[0], b2[1]);
                mma16816(a2[nt], A2l, b2[0], b2[1]);
                mma16816(a2[nt], A2h, b2[2], b2[3]);
            }
        }

        // ---- epilogue: bias + relu + sum, direct STG ----
        {
            const float* bb1 = (const float*)(smem + OFF_BB1);
            const float* bb2 = (const float*)(smem + OFF_BB2);
            const int r0 = tp0 + wid * 16 + (lane >> 2);
            float* ob = out + (size_t)n * 64 * NP;
            #pragma unroll
            for (int nt = 0; nt < 8; nt++) {
                int o0 = nt * 8 + (lane & 3) * 2;
                float u0 = bb1[o0], u1 = bb1[o0 + 1];
                float w0 = bb2[o0], w1 = bb2[o0 + 1];
                if (r0 < NP) {
                    ob[(size_t)o0 * NP + r0]       = fmaxf(a1[nt][0] + u0, 0.f) + fmaxf(a2[nt][0] + w0, 0.f);
                    ob[(size_t)(o0 + 1) * NP + r0] = fmaxf(a1[nt][1] + u1, 0.f) + fmaxf(a2[nt][1] + w1, 0.f);
                }
                if (r0 + 8 < NP) {
                    ob[(size_t)o0 * NP + r0 + 8]       = fmaxf(a1[nt][2] + u0, 0.f) + fmaxf(a2[nt][2] + w0, 0.f);
                    ob[(size_t)(o0 + 1) * NP + r0 + 8] = fmaxf(a1[nt][3] + u1, 0.f) + fmaxf(a2[nt][3] + w1, 0.f);
                }
            }
        }
    }
}

// ---------------------------------------------------------------------------
extern "C" void kernel_launch(void* const* d_in, const int* in_sizes, int n_in,
                              void* d_out, int out_size)
{
    const float* x   = (const float*)d_in[0];
    const float* g1  = (const float*)d_in[1];
    const float* b1g = (const float*)d_in[2];
    const float* w1a = (const float*)d_in[3];
    const float* b1a = (const float*)d_in[4];
    const float* w1b = (const float*)d_in[5];
    const float* b1b = (const float*)d_in[6];
    const float* g2  = (const float*)d_in[7];
    const float* b2g = (const float*)d_in[8];
    const float* w2a = (const float*)d_in[9];
    const float* b2a = (const float*)d_in[10];
    const float* w2b = (const float*)d_in[11];
    const float* b2b = (const float*)d_in[12];
    float* out = (float*)d_out;

    stats1<<<dim3(4, NN), 256>>>(x);
    stats2<<<NCH, 256>>>(g1, b1g, g2, b2g);

    cudaFuncSetAttribute(main_mma, cudaFuncAttributeMaxDynamicSharedMemorySize, SMEM_SZ);
    main_mma<<<dim3(15, NN), THREADS, SMEM_SZ>>>(
        w1a, b1a, w1b, b1b, w2a, b2a, w2b, b2b, out);
}

// round 6
// speedup vs baseline: 2.3696x; 1.1602x over previous
#include <cuda_runtime.h>
#include <cuda_fp16.h>
#include <cstdint>

#define NN   256
#define TT   300
#define NV   25
#define NCH  75
#define NP   (NV * TT)            // 7500
#define MTILE 128                 // points per CTA tile
#define ITER  2                   // tiles per CTA
#define THREADS 256

// parent joint (0-indexed)
__constant__ int c_par[NV] = {1,20,20,2,20,4,5,6,20,8,9,10,0,12,13,14,0,16,17,18,20,22,7,24,11};

// folded BN affine per channel (index = c*25+v)
__device__ float g_sc1[NCH], g_sh1[NCH], g_sc2[NCH], g_sh2[NCH];

// bone / t_bone scratch: [n][ch 0..5][p]
__device__ float g_bone[(size_t)NN * 6 * NP];

// stats partials
#define SBLK 1024
__device__ float g_ps1[NCH * 3 * SBLK];
__device__ float g_pq1[NCH * 3 * SBLK];
__device__ float g_ps2[NCH * 3 * SBLK];
__device__ float g_pq2[NCH * 3 * SBLK];

__device__ __forceinline__ uint32_t s2u(const void* p) {
    uint32_t a;
    asm("{ .reg .u64 t; cvta.to.shared.u64 t, %1; cvt.u32.u64 %0, t; }" : "=r"(a) : "l"(p));
    return a;
}

__device__ __forceinline__ void ldsm4(uint32_t* r, uint32_t addr) {
    asm volatile("ldmatrix.sync.aligned.m8n8.x4.shared.b16 {%0,%1,%2,%3}, [%4];"
                 : "=r"(r[0]), "=r"(r[1]), "=r"(r[2]), "=r"(r[3]) : "r"(addr));
}

__device__ __forceinline__ void mma16816(float* d, const uint32_t* a, uint32_t b0, uint32_t b1) {
    asm volatile(
        "mma.sync.aligned.m16n8k16.row.col.f32.f16.f16.f32 "
        "{%0,%1,%2,%3}, {%4,%5,%6,%7}, {%8,%9}, {%0,%1,%2,%3};"
        : "+f"(d[0]), "+f"(d[1]), "+f"(d[2]), "+f"(d[3])
        : "r"(a[0]), "r"(a[1]), "r"(a[2]), "r"(a[3]), "r"(b0), "r"(b1));
}

// ---------------------------------------------------------------------------
// stats + bone precompute: grid (4 t-chunks, 256 n), 256 threads
// ---------------------------------------------------------------------------
__global__ __launch_bounds__(256) void stats1(const float* __restrict__ x) {
    __shared__ float rows[76][76];
    int tc = blockIdx.x, n = blockIdx.y;
    int t0 = tc * 75;
    int tid = threadIdx.x;

    for (int i = tid; i < 76 * NCH; i += 256) {
        int r = i / NCH, c = i - r * NCH;
        int t = t0 + r;
        rows[r][c] = (t < TT) ? x[((size_t)n * TT + t) * NCH + c] : 0.0f;
    }
    __syncthreads();

    float* bp = g_bone + (size_t)n * 6 * NP;
    for (int i = tid; i < NCH * 75; i += 256) {
        int ch = i / 75, r = i - ch * 75;
        int c = ch / NV, v = ch - c * NV;
        int ci = v * 3 + c, pi = c_par[v] * 3 + c;
        float b = rows[r][ci] - rows[r][pi];
        float d = 0.0f;
        if (t0 + r < TT - 1) d = (rows[r + 1][ci] - rows[r + 1][pi]) - b;
        size_t pidx = (size_t)v * TT + t0 + r;
        bp[(size_t)c * NP + pidx]       = b;
        bp[(size_t)(3 + c) * NP + pidx] = d;
    }

    int g = tid / NCH;
    int ch = tid - g * NCH;
    if (g < 3) {
        int c = ch / NV, v = ch - c * NV;
        int ci = v * 3 + c, pi = c_par[v] * 3 + c;
        float s1 = 0, q1 = 0, s2 = 0, q2 = 0;
        for (int r = g; r < 75; r += 3) {
            float b = rows[r][ci] - rows[r][pi];
            s1 += b; q1 += b * b;
            if (t0 + r < TT - 1) {
                float d = (rows[r + 1][ci] - rows[r + 1][pi]) - b;
                s2 += d; q2 += d * d;
            }
        }
        int idx = (ch * 3 + g) * SBLK + (tc * NN + n);
        g_ps1[idx] = s1; g_pq1[idx] = q1;
        g_ps2[idx] = s2; g_pq2[idx] = q2;
    }
}

__global__ __launch_bounds__(256) void stats2(
    const float* __restrict__ g1, const float* __restrict__ b1,
    const float* __restrict__ g2, const float* __restrict__ b2)
{
    int ch = blockIdx.x;
    int tid = threadIdx.x;
    float s1 = 0, q1 = 0, s2 = 0, q2 = 0;
    for (int g = 0; g < 3; g++) {
        int base = (ch * 3 + g) * SBLK;
        for (int i = tid; i < SBLK; i += 256) {
            s1 += g_ps1[base + i]; q1 += g_pq1[base + i];
            s2 += g_ps2[base + i]; q2 += g_pq2[base + i];
        }
    }
    __shared__ float red[4][256];
    red[0][tid] = s1; red[1][tid] = q1; red[2][tid] = s2; red[3][tid] = q2;
    __syncthreads();
    for (int s = 128; s > 0; s >>= 1) {
        if (tid < s) {
            #pragma unroll
            for (int j = 0; j < 4; j++) red[j][tid] += red[j][tid + s];
        }
        __syncthreads();
    }
    if (tid == 0) {
        const float inv = 1.0f / (float)(NN * TT);
        float m1 = red[0][0] * inv;
        float v1 = red[1][0] * inv - m1 * m1;
        float sc1 = rsqrtf(v1 + 1e-5f) * g1[ch];
        g_sc1[ch] = sc1;
        g_sh1[ch] = b1[ch] - m1 * sc1;
        float m2 = red[2][0] * inv;
        float v2 = red[3][0] * inv - m2 * m2;
        float sc2 = rsqrtf(v2 + 1e-5f) * g2[ch];
        g_sc2[ch] = sc2;
        g_sh2[ch] = b2[ch] - m2 * sc2;
    }
}

// ---------------------------------------------------------------------------
// main kernel: A (activations) single fp16, B (weights) fp16 hi/lo 2-pass
// grid (30, 256), 256 threads, 2 CTAs/SM
// ---------------------------------------------------------------------------
#define ASTR 144                       // A row stride bytes (64 fp16 + pad)
#define BSTR 272                       // B row stride bytes (hi 128 | lo 128 + pad)
#define OFF_A1  0
#define OFF_A2  (OFF_A1 + MTILE * ASTR)
#define OFF_B1  (OFF_A2 + MTILE * ASTR)
#define OFF_B2  (OFF_B1 + 64 * BSTR)
#define OFF_WP1 (OFF_B2 + 64 * BSTR)
#define OFF_WP2 (OFF_WP1 + 1024)
#define OFF_BB1 (OFF_WP2 + 1024)
#define OFF_BB2 (OFF_BB1 + 256)
#define SMEM_SZ (OFF_BB2 + 256)

extern __shared__ char smem[];

__global__ __launch_bounds__(THREADS, 2) void main_mma(
    const float* __restrict__ w1a, const float* __restrict__ b1a,
    const float* __restrict__ w1b, const float* __restrict__ b1b,
    const float* __restrict__ w2a, const float* __restrict__ b2a,
    const float* __restrict__ w2b, const float* __restrict__ b2b,
    float* __restrict__ out)
{
    const int tid  = threadIdx.x;
    const int wid  = tid >> 5, lane = tid & 31;
    const int n    = blockIdx.y;

    // ---- stage weights (fp16 hi/lo split), layer-1 tables, biases ----
    for (int i = tid; i < 64 * 64; i += THREADS) {
        int o = i >> 6, h = i & 63;
        float w = w1b[i];
        __half hi = __float2half_rn(w);
        __half lo = __float2half_rn(w - __half2float(hi));
        *(__half*)(smem + OFF_B1 + o * BSTR + h * 2)       = hi;
        *(__half*)(smem + OFF_B1 + o * BSTR + 128 + h * 2) = lo;
        w = w2b[i];
        hi = __float2half_rn(w);
        lo = __float2half_rn(w - __half2float(hi));
        *(__half*)(smem + OFF_B2 + o * BSTR + h * 2)       = hi;
        *(__half*)(smem + OFF_B2 + o * BSTR + 128 + h * 2) = lo;
    }
    if (tid < 64) {
        *(float4*)(smem + OFF_WP1 + tid * 16) =
            make_float4(w1a[tid * 3], w1a[tid * 3 + 1], w1a[tid * 3 + 2], b1a[tid]);
    } else if (tid < 128) {
        int o = tid - 64;
        *(float4*)(smem + OFF_WP2 + o * 16) =
            make_float4(w2a[o * 3], w2a[o * 3 + 1], w2a[o * 3 + 2], b2a[o]);
    } else if (tid < 192) {
        ((float*)(smem + OFF_BB1))[tid - 128] = b1b[tid - 128];
    } else {
        ((float*)(smem + OFF_BB2))[tid - 192] = b2b[tid - 192];
    }

    const int p    = tid & 127;        // local point (A row)
    const int half = tid >> 7;         // 0/1 : which 16 o-pairs
    const float* bnp = g_bone + (size_t)n * 6 * NP;

    const uint32_t sA1 = s2u(smem + OFF_A1), sA2 = s2u(smem + OFF_A2);
    const uint32_t sB1 = s2u(smem + OFF_B1), sB2 = s2u(smem + OFF_B2);
    const uint32_t aoff = (uint32_t)(wid * 16 + (lane & 15)) * ASTR + (lane >> 4) * 16;
    const uint32_t boff = (uint32_t)(lane & 7) * BSTR + ((lane >> 3) & 1) * 16
                        + ((lane >> 4) & 1) * 128;

    for (int it = 0; it < ITER; it++) {
        const int tp0 = (blockIdx.x * ITER + it) * MTILE;
        // covers staging->H (it=0) and MMA-reads->A-rewrite (it>0)
        __syncthreads();

        // ---- H phase: layer 1 (folded BN) -> fp16 into A smem ----
        {
            const int pg  = tp0 + p;
            const int pgc = (pg < NP) ? pg : (NP - 1);
            const int v   = pgc / TT;
            float z0 = g_sc1[v]          * bnp[pgc]          + g_sh1[v];
            float z1 = g_sc1[NV + v]     * bnp[NP + pgc]     + g_sh1[NV + v];
            float z2 = g_sc1[2 * NV + v] * bnp[2 * NP + pgc] + g_sh1[2 * NV + v];
            float y0 = g_sc2[v]          * bnp[3 * NP + pgc] + g_sh2[v];
            float y1 = g_sc2[NV + v]     * bnp[4 * NP + pgc] + g_sh2[NV + v];
            float y2 = g_sc2[2 * NV + v] * bnp[5 * NP + pgc] + g_sh2[2 * NV + v];

            const uint32_t rowb = (uint32_t)p * ASTR;
            #pragma unroll
            for (int j = 0; j < 16; j++) {
                int oo = half * 16 + ((j + (lane >> 3)) & 15);
                int o0 = oo * 2;
                float4 wp = *(const float4*)(smem + OFF_WP1 + o0 * 16);
                float4 wq = *(const float4*)(smem + OFF_WP1 + (o0 + 1) * 16);
                float h0 = fmaxf(fmaf(wp.x, z0, fmaf(wp.y, z1, fmaf(wp.z, z2, wp.w))), 0.0f);
                float h1 = fmaxf(fmaf(wq.x, z0, fmaf(wq.y, z1, fmaf(wq.z, z2, wq.w))), 0.0f);
                uint32_t pk;
                asm("cvt.rn.f16x2.f32 %0, %1, %2;" : "=r"(pk) : "f"(h1), "f"(h0));
                *(uint32_t*)(smem + OFF_A1 + rowb + oo * 4) = pk;

                float4 vp = *(const float4*)(smem + OFF_WP2 + o0 * 16);
                float4 vq = *(const float4*)(smem + OFF_WP2 + (o0 + 1) * 16);
                float g0  = fmaxf(fmaf(vp.x, y0, fmaf(vp.y, y1, fmaf(vp.z, y2, vp.w))), 0.0f);
                float g1v = fmaxf(fmaf(vq.x, y0, fmaf(vq.y, y1, fmaf(vq.z, y2, vq.w))), 0.0f);
                asm("cvt.rn.f16x2.f32 %0, %1, %2;" : "=r"(pk) : "f"(g1v), "f"(g0));
                *(uint32_t*)(smem + OFF_A2 + rowb + oo * 4) = pk;
            }
        }
        __syncthreads();

        // ---- MMA phase: per warp m16 x n64, fp16 2-pass (B hi + B lo) ----
        float a1[8][4], a2[8][4];
        #pragma unroll
        for (int ntt = 0; ntt < 8; ntt++)
            #pragma unroll
            for (int q = 0; q < 4; q++) { a1[ntt][q] = 0.f; a2[ntt][q] = 0.f; }

        #pragma unroll
        for (int kc = 0; kc < 4; kc++) {
            uint32_t A1[4], A2[4];
            ldsm4(A1, sA1 + aoff + kc * 32);
            ldsm4(A2, sA2 + aoff + kc * 32);
            #pragma unroll
            for (int nt = 0; nt < 8; nt++) {
                uint32_t b1[4], b2[4];
                ldsm4(b1, sB1 + boff + (uint32_t)nt * 8 * BSTR + kc * 32);
                ldsm4(b2, sB2 + boff + (uint32_t)nt * 8 * BSTR + kc * 32);
                mma16816(a1[nt], A1, b1[0], b1[1]);   // A * B_hi
                mma16816(a1[nt], A1, b1[2], b1[3]);   // A * B_lo
                mma16816(a2[nt], A2, b2[0], b2[1]);
                mma16816(a2[nt], A2, b2[2], b2[3]);
            }
        }

        // ---- epilogue: bias + relu + sum, direct STG ----
        {
            const float* bb1 = (const float*)(smem + OFF_BB1);
            const float* bb2 = (const float*)(smem + OFF_BB2);
            const int r0 = tp0 + wid * 16 + (lane >> 2);
            float* ob = out + (size_t)n * 64 * NP;
            #pragma unroll
            for (int nt = 0; nt < 8; nt++) {
                int o0 = nt * 8 + (lane & 3) * 2;
                float u0 = bb1[o0], u1 = bb1[o0 + 1];
                float w0 = bb2[o0], w1 = bb2[o0 + 1];
                if (r0 < NP) {
                    ob[(size_t)o0 * NP + r0]       = fmaxf(a1[nt][0] + u0, 0.f) + fmaxf(a2[nt][0] + w0, 0.f);
                    ob[(size_t)(o0 + 1) * NP + r0] = fmaxf(a1[nt][1] + u1, 0.f) + fmaxf(a2[nt][1] + w1, 0.f);
                }
                if (r0 + 8 < NP) {
                    ob[(size_t)o0 * NP + r0 + 8]       = fmaxf(a1[nt][2] + u0, 0.f) + fmaxf(a2[nt][2] + w0, 0.f);
                    ob[(size_t)(o0 + 1) * NP + r0 + 8] = fmaxf(a1[nt][3] + u1, 0.f) + fmaxf(a2[nt][3] + w1, 0.f);
                }
            }
        }
    }
}

// ---------------------------------------------------------------------------
extern "C" void kernel_launch(void* const* d_in, const int* in_sizes, int n_in,
                              void* d_out, int out_size)
{
    const float* x   = (const float*)d_in[0];
    const float* g1  = (const float*)d_in[1];
    const float* b1g = (const float*)d_in[2];
    const float* w1a = (const float*)d_in[3];
    const float* b1a = (const float*)d_in[4];
    const float* w1b = (const float*)d_in[5];
    const float* b1b = (const float*)d_in[6];
    const float* g2  = (const float*)d_in[7];
    const float* b2g = (const float*)d_in[8];
    const float* w2a = (const float*)d_in[9];
    const float* b2a = (const float*)d_in[10];
    const float* w2b = (const float*)d_in[11];
    const float* b2b = (const float*)d_in[12];
    float* out = (float*)d_out;

    stats1<<<dim3(4, NN), 256>>>(x);
    stats2<<<NCH, 256>>>(g1, b1g, g2, b2g);

    cudaFuncSetAttribute(main_mma, cudaFuncAttributeMaxDynamicSharedMemorySize, SMEM_SZ);
    main_mma<<<dim3(30, NN), THREADS, SMEM_SZ>>>(
        w1a, b1a, w1b, b1b, w2a, b2a, w2b, b2b, out);
}

// round 7
// speedup vs baseline: 2.8029x; 1.1828x over previous
#include <cuda_runtime.h>
#include <cuda_fp16.h>
#include <cstdint>

#define NN   256
#define TT   300
#define NV   25
#define NCH  75
#define NP   (NV * TT)            // 7500
#define MTILE 128                 // points per CTA tile
#define ITER  2                   // tiles per CTA
#define THREADS 256

// parent joint (0-indexed)
__constant__ int c_par[NV] = {1,20,20,2,20,4,5,6,20,8,9,10,0,12,13,14,0,16,17,18,20,22,7,24,11};

// folded BN affine per channel (index = c*25+v)
__device__ float g_sc1[NCH], g_sh1[NCH], g_sc2[NCH], g_sh2[NCH];

// bone / t_bone scratch: [n][ch 0..5][p]
__device__ float g_bone[(size_t)NN * 6 * NP];

// stats partials
#define SBLK 1024
__device__ float g_ps1[NCH * 3 * SBLK];
__device__ float g_pq1[NCH * 3 * SBLK];
__device__ float g_ps2[NCH * 3 * SBLK];
__device__ float g_pq2[NCH * 3 * SBLK];

__device__ __forceinline__ uint32_t s2u(const void* p) {
    uint32_t a;
    asm("{ .reg .u64 t; cvta.to.shared.u64 t, %1; cvt.u32.u64 %0, t; }" : "=r"(a) : "l"(p));
    return a;
}

__device__ __forceinline__ void ldsm4(uint32_t* r, uint32_t addr) {
    asm volatile("ldmatrix.sync.aligned.m8n8.x4.shared.b16 {%0,%1,%2,%3}, [%4];"
                 : "=r"(r[0]), "=r"(r[1]), "=r"(r[2]), "=r"(r[3]) : "r"(addr));
}

__device__ __forceinline__ void mma16816(float* d, const uint32_t* a, uint32_t b0, uint32_t b1) {
    asm volatile(
        "mma.sync.aligned.m16n8k16.row.col.f32.f16.f16.f32 "
        "{%0,%1,%2,%3}, {%4,%5,%6,%7}, {%8,%9}, {%0,%1,%2,%3};"
        : "+f"(d[0]), "+f"(d[1]), "+f"(d[2]), "+f"(d[3])
        : "r"(a[0]), "r"(a[1]), "r"(a[2]), "r"(a[3]), "r"(b0), "r"(b1));
}

// ---------------------------------------------------------------------------
// stats + bone precompute: grid (4 t-chunks, 256 n), 256 threads
// ---------------------------------------------------------------------------
__global__ __launch_bounds__(256) void stats1(const float* __restrict__ x) {
    __shared__ float rows[76][76];
    int tc = blockIdx.x, n = blockIdx.y;
    int t0 = tc * 75;
    int tid = threadIdx.x;

    for (int i = tid; i < 76 * NCH; i += 256) {
        int r = i / NCH, c = i - r * NCH;
        int t = t0 + r;
        rows[r][c] = (t < TT) ? x[((size_t)n * TT + t) * NCH + c] : 0.0f;
    }
    __syncthreads();

    float* bp = g_bone + (size_t)n * 6 * NP;
    for (int i = tid; i < NCH * 75; i += 256) {
        int ch = i / 75, r = i - ch * 75;
        int c = ch / NV, v = ch - c * NV;
        int ci = v * 3 + c, pi = c_par[v] * 3 + c;
        float b = rows[r][ci] - rows[r][pi];
        float d = 0.0f;
        if (t0 + r < TT - 1) d = (rows[r + 1][ci] - rows[r + 1][pi]) - b;
        size_t pidx = (size_t)v * TT + t0 + r;
        bp[(size_t)c * NP + pidx]       = b;
        bp[(size_t)(3 + c) * NP + pidx] = d;
    }

    int g = tid / NCH;
    int ch = tid - g * NCH;
    if (g < 3) {
        int c = ch / NV, v = ch - c * NV;
        int ci = v * 3 + c, pi = c_par[v] * 3 + c;
        float s1 = 0, q1 = 0, s2 = 0, q2 = 0;
        for (int r = g; r < 75; r += 3) {
            float b = rows[r][ci] - rows[r][pi];
            s1 += b; q1 += b * b;
            if (t0 + r < TT - 1) {
                float d = (rows[r + 1][ci] - rows[r + 1][pi]) - b;
                s2 += d; q2 += d * d;
            }
        }
        int idx = (ch * 3 + g) * SBLK + (tc * NN + n);
        g_ps1[idx] = s1; g_pq1[idx] = q1;
        g_ps2[idx] = s2; g_pq2[idx] = q2;
    }
}

__global__ __launch_bounds__(256) void stats2(
    const float* __restrict__ g1, const float* __restrict__ b1,
    const float* __restrict__ g2, const float* __restrict__ b2)
{
    int ch = blockIdx.x;
    int tid = threadIdx.x;
    float s1 = 0, q1 = 0, s2 = 0, q2 = 0;
    for (int g = 0; g < 3; g++) {
        int base = (ch * 3 + g) * SBLK;
        for (int i = tid; i < SBLK; i += 256) {
            s1 += g_ps1[base + i]; q1 += g_pq1[base + i];
            s2 += g_ps2[base + i]; q2 += g_pq2[base + i];
        }
    }
    __shared__ float red[4][256];
    red[0][tid] = s1; red[1][tid] = q1; red[2][tid] = s2; red[3][tid] = q2;
    __syncthreads();
    for (int s = 128; s > 0; s >>= 1) {
        if (tid < s) {
            #pragma unroll
            for (int j = 0; j < 4; j++) red[j][tid] += red[j][tid + s];
        }
        __syncthreads();
    }
    if (tid == 0) {
        const float inv = 1.0f / (float)(NN * TT);
        float m1 = red[0][0] * inv;
        float v1 = red[1][0] * inv - m1 * m1;
        float sc1 = rsqrtf(v1 + 1e-5f) * g1[ch];
        g_sc1[ch] = sc1;
        g_sh1[ch] = b1[ch] - m1 * sc1;
        float m2 = red[2][0] * inv;
        float v2 = red[3][0] * inv - m2 * m2;
        float sc2 = rsqrtf(v2 + 1e-5f) * g2[ch];
        g_sc2[ch] = sc2;
        g_sh2[ch] = b2[ch] - m2 * sc2;
    }
}

// ---------------------------------------------------------------------------
// main kernel: A (activations) fp16, B = fused weight tile (rows 0-63 W1b-hi,
// rows 64-127 W2b-hi), single-pass fp16 MMA per branch.
// grid (30, 256), 256 threads, 2 CTAs/SM
// ---------------------------------------------------------------------------
#define ASTR 144                       // A row stride bytes (64 fp16 + pad)
#define BSTR 144                       // B row stride bytes (64 fp16 + pad)
#define OFF_A1  0
#define OFF_A2  (OFF_A1 + MTILE * ASTR)
#define OFF_B   (OFF_A2 + MTILE * ASTR)
#define OFF_WP1 (OFF_B + 128 * BSTR)
#define OFF_WP2 (OFF_WP1 + 1024)
#define OFF_BB1 (OFF_WP2 + 1024)
#define OFF_BB2 (OFF_BB1 + 256)
#define SMEM_SZ (OFF_BB2 + 256)

extern __shared__ char smem[];

__global__ __launch_bounds__(THREADS, 2) void main_mma(
    const float* __restrict__ w1a, const float* __restrict__ b1a,
    const float* __restrict__ w1b, const float* __restrict__ b1b,
    const float* __restrict__ w2a, const float* __restrict__ b2a,
    const float* __restrict__ w2b, const float* __restrict__ b2b,
    float* __restrict__ out)
{
    const int tid  = threadIdx.x;
    const int wid  = tid >> 5, lane = tid & 31;
    const int n    = blockIdx.y;

    // ---- stage fused weight tile (fp16), layer-1 tables, biases ----
    for (int i = tid; i < 64 * 64; i += THREADS) {
        int o = i >> 6, h = i & 63;
        *(__half*)(smem + OFF_B + o * BSTR + h * 2)          = __float2half_rn(w1b[i]);
        *(__half*)(smem + OFF_B + (o + 64) * BSTR + h * 2)   = __float2half_rn(w2b[i]);
    }
    if (tid < 64) {
        *(float4*)(smem + OFF_WP1 + tid * 16) =
            make_float4(w1a[tid * 3], w1a[tid * 3 + 1], w1a[tid * 3 + 2], b1a[tid]);
    } else if (tid < 128) {
        int o = tid - 64;
        *(float4*)(smem + OFF_WP2 + o * 16) =
            make_float4(w2a[o * 3], w2a[o * 3 + 1], w2a[o * 3 + 2], b2a[o]);
    } else if (tid < 192) {
        ((float*)(smem + OFF_BB1))[tid - 128] = b1b[tid - 128];
    } else {
        ((float*)(smem + OFF_BB2))[tid - 192] = b2b[tid - 192];
    }

    const int p    = tid & 127;        // local point (A row)
    const int half = tid >> 7;         // 0/1 : which 16 o-pairs
    const float* bnp = g_bone + (size_t)n * 6 * NP;

    const uint32_t sA1 = s2u(smem + OFF_A1), sA2 = s2u(smem + OFF_A2);
    const uint32_t sB  = s2u(smem + OFF_B);
    const uint32_t aoff = (uint32_t)(wid * 16 + (lane & 15)) * ASTR + (lane >> 4) * 16;
    // matrices 0,1: branch1 rows (k 0-7 / 8-15); matrices 2,3: branch2 rows (+64*BSTR)
    const uint32_t boff = (uint32_t)(lane & 7) * BSTR + ((lane >> 3) & 1) * 16
                        + ((lane >> 4) & 1) * (64 * BSTR);

    for (int it = 0; it < ITER; it++) {
        const int tp0 = (blockIdx.x * ITER + it) * MTILE;
        // covers staging->H (it=0) and MMA-reads->A-rewrite (it>0)
        __syncthreads();

        // ---- H phase: layer 1 (folded BN) -> fp16 into A smem ----
        {
            const int pg  = tp0 + p;
            const int pgc = (pg < NP) ? pg : (NP - 1);
            const int v   = pgc / TT;
            float z0 = g_sc1[v]          * bnp[pgc]          + g_sh1[v];
            float z1 = g_sc1[NV + v]     * bnp[NP + pgc]     + g_sh1[NV + v];
            float z2 = g_sc1[2 * NV + v] * bnp[2 * NP + pgc] + g_sh1[2 * NV + v];
            float y0 = g_sc2[v]          * bnp[3 * NP + pgc] + g_sh2[v];
            float y1 = g_sc2[NV + v]     * bnp[4 * NP + pgc] + g_sh2[NV + v];
            float y2 = g_sc2[2 * NV + v] * bnp[5 * NP + pgc] + g_sh2[2 * NV + v];

            const uint32_t rowb = (uint32_t)p * ASTR;
            #pragma unroll
            for (int j = 0; j < 16; j++) {
                int oo = half * 16 + ((j + (lane >> 3)) & 15);
                int o0 = oo * 2;
                float4 wp = *(const float4*)(smem + OFF_WP1 + o0 * 16);
                float4 wq = *(const float4*)(smem + OFF_WP1 + (o0 + 1) * 16);
                float h0 = fmaxf(fmaf(wp.x, z0, fmaf(wp.y, z1, fmaf(wp.z, z2, wp.w))), 0.0f);
                float h1 = fmaxf(fmaf(wq.x, z0, fmaf(wq.y, z1, fmaf(wq.z, z2, wq.w))), 0.0f);
                uint32_t pk;
                asm("cvt.rn.f16x2.f32 %0, %1, %2;" : "=r"(pk) : "f"(h1), "f"(h0));
                *(uint32_t*)(smem + OFF_A1 + rowb + oo * 4) = pk;

                float4 vp = *(const float4*)(smem + OFF_WP2 + o0 * 16);
                float4 vq = *(const float4*)(smem + OFF_WP2 + (o0 + 1) * 16);
                float g0  = fmaxf(fmaf(vp.x, y0, fmaf(vp.y, y1, fmaf(vp.z, y2, vp.w))), 0.0f);
                float g1v = fmaxf(fmaf(vq.x, y0, fmaf(vq.y, y1, fmaf(vq.z, y2, vq.w))), 0.0f);
                asm("cvt.rn.f16x2.f32 %0, %1, %2;" : "=r"(pk) : "f"(g1v), "f"(g0));
                *(uint32_t*)(smem + OFF_A2 + rowb + oo * 4) = pk;
            }
        }
        __syncthreads();

        // ---- MMA phase: per warp m16 x n64 x 2 branches, single-pass fp16 ----
        float a1[8][4], a2[8][4];
        #pragma unroll
        for (int ntt = 0; ntt < 8; ntt++)
            #pragma unroll
            for (int q = 0; q < 4; q++) { a1[ntt][q] = 0.f; a2[ntt][q] = 0.f; }

        #pragma unroll
        for (int kc = 0; kc < 4; kc++) {
            uint32_t A1[4], A2[4];
            ldsm4(A1, sA1 + aoff + kc * 32);
            ldsm4(A2, sA2 + aoff + kc * 32);
            #pragma unroll
            for (int nt = 0; nt < 8; nt++) {
                uint32_t bb[4];
                ldsm4(bb, sB + boff + (uint32_t)nt * 8 * BSTR + kc * 32);
                mma16816(a1[nt], A1, bb[0], bb[1]);   // branch 1
                mma16816(a2[nt], A2, bb[2], bb[3]);   // branch 2
            }
        }

        // ---- epilogue: bias + relu + sum, direct STG ----
        {
            const float* bb1 = (const float*)(smem + OFF_BB1);
            const float* bb2 = (const float*)(smem + OFF_BB2);
            const int r0 = tp0 + wid * 16 + (lane >> 2);
            float* ob = out + (size_t)n * 64 * NP;
            #pragma unroll
            for (int nt = 0; nt < 8; nt++) {
                int o0 = nt * 8 + (lane & 3) * 2;
                float u0 = bb1[o0], u1 = bb1[o0 + 1];
                float w0 = bb2[o0], w1 = bb2[o0 + 1];
                if (r0 < NP) {
                    ob[(size_t)o0 * NP + r0]       = fmaxf(a1[nt][0] + u0, 0.f) + fmaxf(a2[nt][0] + w0, 0.f);
                    ob[(size_t)(o0 + 1) * NP + r0] = fmaxf(a1[nt][1] + u1, 0.f) + fmaxf(a2[nt][1] + w1, 0.f);
                }
                if (r0 + 8 < NP) {
                    ob[(size_t)o0 * NP + r0 + 8]       = fmaxf(a1[nt][2] + u0, 0.f) + fmaxf(a2[nt][2] + w0, 0.f);
                    ob[(size_t)(o0 + 1) * NP + r0 + 8] = fmaxf(a1[nt][3] + u1, 0.f) + fmaxf(a2[nt][3] + w1, 0.f);
                }
            }
        }
    }
}

// ---------------------------------------------------------------------------
extern "C" void kernel_launch(void* const* d_in, const int* in_sizes, int n_in,
                              void* d_out, int out_size)
{
    const float* x   = (const float*)d_in[0];
    const float* g1  = (const float*)d_in[1];
    const float* b1g = (const float*)d_in[2];
    const float* w1a = (const float*)d_in[3];
    const float* b1a = (const float*)d_in[4];
    const float* w1b = (const float*)d_in[5];
    const float* b1b = (const float*)d_in[6];
    const float* g2  = (const float*)d_in[7];
    const float* b2g = (const float*)d_in[8];
    const float* w2a = (const float*)d_in[9];
    const float* b2a = (const float*)d_in[10];
    const float* w2b = (const float*)d_in[11];
    const float* b2b = (const float*)d_in[12];
    float* out = (float*)d_out;

    stats1<<<dim3(4, NN), 256>>>(x);
    stats2<<<NCH, 256>>>(g1, b1g, g2, b2g);

    cudaFuncSetAttribute(main_mma, cudaFuncAttributeMaxDynamicSharedMemorySize, SMEM_SZ);
    main_mma<<<dim3(30, NN), THREADS, SMEM_SZ>>>(
        w1a, b1a, w1b, b1b, w2a, b2a, w2b, b2b, out);
}

// round 8
// speedup vs baseline: 2.8073x; 1.0016x over previous
#include <cuda_runtime.h>
#include <cuda_fp16.h>
#include <cstdint>

#define NN   256
#define TT   300
#define NV   25
#define NCH  75
#define NP   (NV * TT)            // 7500
#define MTILE 128                 // points per CTA tile
#define ITER  2                   // tiles per CTA
#define THREADS 256

// parent joint (0-indexed)
__constant__ int c_par[NV] = {1,20,20,2,20,4,5,6,20,8,9,10,0,12,13,14,0,16,17,18,20,22,7,24,11};

// folded BN affine per channel (index = c*25+v)
__device__ float g_sc1[NCH], g_sh1[NCH], g_sc2[NCH], g_sh2[NCH];

// bone / t_bone scratch: [n][ch 0..5][p]
__device__ float g_bone[(size_t)NN * 6 * NP];

// stats partials
#define SBLK 1024
__device__ float g_ps1[NCH * 3 * SBLK];
__device__ float g_pq1[NCH * 3 * SBLK];
__device__ float g_ps2[NCH * 3 * SBLK];
__device__ float g_pq2[NCH * 3 * SBLK];

__device__ __forceinline__ uint32_t s2u(const void* p) {
    uint32_t a;
    asm("{ .reg .u64 t; cvta.to.shared.u64 t, %1; cvt.u32.u64 %0, t; }" : "=r"(a) : "l"(p));
    return a;
}

__device__ __forceinline__ void ldsm4(uint32_t* r, uint32_t addr) {
    asm volatile("ldmatrix.sync.aligned.m8n8.x4.shared.b16 {%0,%1,%2,%3}, [%4];"
                 : "=r"(r[0]), "=r"(r[1]), "=r"(r[2]), "=r"(r[3]) : "r"(addr));
}

__device__ __forceinline__ void mma16816(float* d, const uint32_t* a, uint32_t b0, uint32_t b1) {
    asm volatile(
        "mma.sync.aligned.m16n8k16.row.col.f32.f16.f16.f32 "
        "{%0,%1,%2,%3}, {%4,%5,%6,%7}, {%8,%9}, {%0,%1,%2,%3};"
        : "+f"(d[0]), "+f"(d[1]), "+f"(d[2]), "+f"(d[3])
        : "r"(a[0]), "r"(a[1]), "r"(a[2]), "r"(a[3]), "r"(b0), "r"(b1));
}

// ---------------------------------------------------------------------------
// stats + bone precompute: grid (4 t-chunks, 256 n), 256 threads
// ---------------------------------------------------------------------------
__global__ __launch_bounds__(256) void stats1(const float* __restrict__ x) {
    __shared__ float rows[76][76];
    int tc = blockIdx.x, n = blockIdx.y;
    int t0 = tc * 75;
    int tid = threadIdx.x;

    for (int i = tid; i < 76 * NCH; i += 256) {
        int r = i / NCH, c = i - r * NCH;
        int t = t0 + r;
        rows[r][c] = (t < TT) ? x[((size_t)n * TT + t) * NCH + c] : 0.0f;
    }
    __syncthreads();

    float* bp = g_bone + (size_t)n * 6 * NP;
    for (int i = tid; i < NCH * 75; i += 256) {
        int ch = i / 75, r = i - ch * 75;
        int c = ch / NV, v = ch - c * NV;
        int ci = v * 3 + c, pi = c_par[v] * 3 + c;
        float b = rows[r][ci] - rows[r][pi];
        float d = 0.0f;
        if (t0 + r < TT - 1) d = (rows[r + 1][ci] - rows[r + 1][pi]) - b;
        size_t pidx = (size_t)v * TT + t0 + r;
        bp[(size_t)c * NP + pidx]       = b;
        bp[(size_t)(3 + c) * NP + pidx] = d;
    }

    int g = tid / NCH;
    int ch = tid - g * NCH;
    if (g < 3) {
        int c = ch / NV, v = ch - c * NV;
        int ci = v * 3 + c, pi = c_par[v] * 3 + c;
        float s1 = 0, q1 = 0, s2 = 0, q2 = 0;
        for (int r = g; r < 75; r += 3) {
            float b = rows[r][ci] - rows[r][pi];
            s1 += b; q1 += b * b;
            if (t0 + r < TT - 1) {
                float d = (rows[r + 1][ci] - rows[r + 1][pi]) - b;
                s2 += d; q2 += d * d;
            }
        }
        int idx = (ch * 3 + g) * SBLK + (tc * NN + n);
        g_ps1[idx] = s1; g_pq1[idx] = q1;
        g_ps2[idx] = s2; g_pq2[idx] = q2;
    }
}

__global__ __launch_bounds__(256) void stats2(
    const float* __restrict__ g1, const float* __restrict__ b1,
    const float* __restrict__ g2, const float* __restrict__ b2)
{
    int ch = blockIdx.x;
    int tid = threadIdx.x;
    float s1 = 0, q1 = 0, s2 = 0, q2 = 0;
    for (int g = 0; g < 3; g++) {
        int base = (ch * 3 + g) * SBLK;
        for (int i = tid; i < SBLK; i += 256) {
            s1 += g_ps1[base + i]; q1 += g_pq1[base + i];
            s2 += g_ps2[base + i]; q2 += g_pq2[base + i];
        }
    }
    __shared__ float red[4][256];
    red[0][tid] = s1; red[1][tid] = q1; red[2][tid] = s2; red[3][tid] = q2;
    __syncthreads();
    for (int s = 128; s > 0; s >>= 1) {
        if (tid < s) {
            #pragma unroll
            for (int j = 0; j < 4; j++) red[j][tid] += red[j][tid + s];
        }
        __syncthreads();
    }
    if (tid == 0) {
        const float inv = 1.0f / (float)(NN * TT);
        float m1 = red[0][0] * inv;
        float v1 = red[1][0] * inv - m1 * m1;
        float sc1 = rsqrtf(v1 + 1e-5f) * g1[ch];
        g_sc1[ch] = sc1;
        g_sh1[ch] = b1[ch] - m1 * sc1;
        float m2 = red[2][0] * inv;
        float v2 = red[3][0] * inv - m2 * m2;
        float sc2 = rsqrtf(v2 + 1e-5f) * g2[ch];
        g_sc2[ch] = sc2;
        g_sh2[ch] = b2[ch] - m2 * sc2;
    }
}

// ---------------------------------------------------------------------------
// main kernel: layer-1 weights in registers, z/y broadcast via smem;
// B = fused weight tile (rows 0-63 W1b, 64-127 W2b) fp16, single-pass MMA.
// grid (30, 256), 256 threads, 2 CTAs/SM
// ---------------------------------------------------------------------------
#define ASTR 144                       // A row stride bytes (64 fp16 + pad)
#define BSTR 144                       // B row stride bytes
#define OFF_A1  0
#define OFF_A2  (OFF_A1 + MTILE * ASTR)
#define OFF_B   (OFF_A2 + MTILE * ASTR)
#define OFF_ZS  (OFF_B + 128 * BSTR)   // z/y staging: 128 points x 32 bytes
#define OFF_BB1 (OFF_ZS + MTILE * 32)
#define OFF_BB2 (OFF_BB1 + 256)
#define SMEM_SZ (OFF_BB2 + 256)

extern __shared__ char smem[];

__global__ __launch_bounds__(THREADS, 2) void main_mma(
    const float* __restrict__ w1a, const float* __restrict__ b1a,
    const float* __restrict__ w1b, const float* __restrict__ b1b,
    const float* __restrict__ w2a, const float* __restrict__ b2a,
    const float* __restrict__ w2b, const float* __restrict__ b2b,
    float* __restrict__ out)
{
    const int tid  = threadIdx.x;
    const int wid  = tid >> 5, lane = tid & 31;
    const int n    = blockIdx.y;

    // ---- stage fused weight tile (fp16) + biases ----
    for (int i = tid; i < 64 * 64; i += THREADS) {
        int o = i >> 6, h = i & 63;
        *(__half*)(smem + OFF_B + o * BSTR + h * 2)        = __float2half_rn(w1b[i]);
        *(__half*)(smem + OFF_B + (o + 64) * BSTR + h * 2) = __float2half_rn(w2b[i]);
    }
    if (tid < 64) {
        ((float*)(smem + OFF_BB1))[tid] = b1b[tid];
    } else if (tid < 128) {
        ((float*)(smem + OFF_BB2))[tid - 64] = b2b[tid - 64];
    }

    // ---- layer-1 weights in registers: this thread owns o-pair oo = lane ----
    const int o0 = lane * 2, o1 = lane * 2 + 1;
    const float4 wp1 = make_float4(w1a[o0*3], w1a[o0*3+1], w1a[o0*3+2], b1a[o0]);
    const float4 wq1 = make_float4(w1a[o1*3], w1a[o1*3+1], w1a[o1*3+2], b1a[o1]);
    const float4 wp2 = make_float4(w2a[o0*3], w2a[o0*3+1], w2a[o0*3+2], b2a[o0]);
    const float4 wq2 = make_float4(w2a[o1*3], w2a[o1*3+1], w2a[o1*3+2], b2a[o1]);

    const float* bnp = g_bone + (size_t)n * 6 * NP;

    const uint32_t sA1 = s2u(smem + OFF_A1), sA2 = s2u(smem + OFF_A2);
    const uint32_t sB  = s2u(smem + OFF_B);
    const uint32_t aoff = (uint32_t)(wid * 16 + (lane & 15)) * ASTR + (lane >> 4) * 16;
    // matrices 0,1: branch1 rows; matrices 2,3: branch2 rows (+64*BSTR)
    const uint32_t boff = (uint32_t)(lane & 7) * BSTR + ((lane >> 3) & 1) * 16
                        + ((lane >> 4) & 1) * (64 * BSTR);

    for (int it = 0; it < ITER; it++) {
        const int tp0 = (blockIdx.x * ITER + it) * MTILE;
        // A-rewrite safety vs previous MMA reads; staging visibility on it=0
        __syncthreads();

        // ---- z/y prep: one thread per point -> smem (32B/point) ----
        if (tid < MTILE) {
            const int pg  = tp0 + tid;
            const int pgc = (pg < NP) ? pg : (NP - 1);
            const int v   = pgc / TT;
            float z0 = g_sc1[v]          * bnp[pgc]          + g_sh1[v];
            float z1 = g_sc1[NV + v]     * bnp[NP + pgc]     + g_sh1[NV + v];
            float z2 = g_sc1[2 * NV + v] * bnp[2 * NP + pgc] + g_sh1[2 * NV + v];
            float y0 = g_sc2[v]          * bnp[3 * NP + pgc] + g_sh2[v];
            float y1 = g_sc2[NV + v]     * bnp[4 * NP + pgc] + g_sh2[NV + v];
            float y2 = g_sc2[2 * NV + v] * bnp[5 * NP + pgc] + g_sh2[2 * NV + v];
            *(float4*)(smem + OFF_ZS + tid * 32)      = make_float4(z0, z1, z2, 0.f);
            *(float4*)(smem + OFF_ZS + tid * 32 + 16) = make_float4(y0, y1, y2, 0.f);
        }
        __syncthreads();

        // ---- H phase: each thread = o-pair oo for 16 points (z/y broadcast) ----
        #pragma unroll
        for (int i = 0; i < 16; i++) {
            const int p = wid * 16 + i;
            float4 z = *(const float4*)(smem + OFF_ZS + p * 32);
            float4 y = *(const float4*)(smem + OFF_ZS + p * 32 + 16);
            float h0 = fmaxf(fmaf(wp1.x, z.x, fmaf(wp1.y, z.y, fmaf(wp1.z, z.z, wp1.w))), 0.0f);
            float h1 = fmaxf(fmaf(wq1.x, z.x, fmaf(wq1.y, z.y, fmaf(wq1.z, z.z, wq1.w))), 0.0f);
            uint32_t pk;
            asm("cvt.rn.f16x2.f32 %0, %1, %2;" : "=r"(pk) : "f"(h1), "f"(h0));
            *(uint32_t*)(smem + OFF_A1 + p * ASTR + lane * 4) = pk;

            float g0 = fmaxf(fmaf(wp2.x, y.x, fmaf(wp2.y, y.y, fmaf(wp2.z, y.z, wp2.w))), 0.0f);
            float g1 = fmaxf(fmaf(wq2.x, y.x, fmaf(wq2.y, y.y, fmaf(wq2.z, y.z, wq2.w))), 0.0f);
            asm("cvt.rn.f16x2.f32 %0, %1, %2;" : "=r"(pk) : "f"(g1), "f"(g0));
            *(uint32_t*)(smem + OFF_A2 + p * ASTR + lane * 4) = pk;
        }
        __syncthreads();

        // ---- MMA phase: per warp m16 x n64 x 2 branches, single-pass fp16 ----
        float a1[8][4], a2[8][4];
        #pragma unroll
        for (int ntt = 0; ntt < 8; ntt++)
            #pragma unroll
            for (int q = 0; q < 4; q++) { a1[ntt][q] = 0.f; a2[ntt][q] = 0.f; }

        #pragma unroll
        for (int kc = 0; kc < 4; kc++) {
            uint32_t A1[4], A2[4];
            ldsm4(A1, sA1 + aoff + kc * 32);
            ldsm4(A2, sA2 + aoff + kc * 32);
            #pragma unroll
            for (int nt = 0; nt < 8; nt++) {
                uint32_t bb[4];
                ldsm4(bb, sB + boff + (uint32_t)nt * 8 * BSTR + kc * 32);
                mma16816(a1[nt], A1, bb[0], bb[1]);   // branch 1
                mma16816(a2[nt], A2, bb[2], bb[3]);   // branch 2
            }
        }

        // ---- epilogue: bias + relu + sum, direct STG ----
        {
            const float* bb1 = (const float*)(smem + OFF_BB1);
            const float* bb2 = (const float*)(smem + OFF_BB2);
            const int r0 = tp0 + wid * 16 + (lane >> 2);
            float* ob = out + (size_t)n * 64 * NP;
            #pragma unroll
            for (int nt = 0; nt < 8; nt++) {
                int oc = nt * 8 + (lane & 3) * 2;
                float u0 = bb1[oc], u1 = bb1[oc + 1];
                float w0 = bb2[oc], w1 = bb2[oc + 1];
                if (r0 < NP) {
                    ob[(size_t)oc * NP + r0]       = fmaxf(a1[nt][0] + u0, 0.f) + fmaxf(a2[nt][0] + w0, 0.f);
                    ob[(size_t)(oc + 1) * NP + r0] = fmaxf(a1[nt][1] + u1, 0.f) + fmaxf(a2[nt][1] + w1, 0.f);
                }
                if (r0 + 8 < NP) {
                    ob[(size_t)oc * NP + r0 + 8]       = fmaxf(a1[nt][2] + u0, 0.f) + fmaxf(a2[nt][2] + w0, 0.f);
                    ob[(size_t)(oc + 1) * NP + r0 + 8] = fmaxf(a1[nt][3] + u1, 0.f) + fmaxf(a2[nt][3] + w1, 0.f);
                }
            }
        }
    }
}

// ---------------------------------------------------------------------------
extern "C" void kernel_launch(void* const* d_in, const int* in_sizes, int n_in,
                              void* d_out, int out_size)
{
    const float* x   = (const float*)d_in[0];
    const float* g1  = (const float*)d_in[1];
    const float* b1g = (const float*)d_in[2];
    const float* w1a = (const float*)d_in[3];
    const float* b1a = (const float*)d_in[4];
    const float* w1b = (const float*)d_in[5];
    const float* b1b = (const float*)d_in[6];
    const float* g2  = (const float*)d_in[7];
    const float* b2g = (const float*)d_in[8];
    const float* w2a = (const float*)d_in[9];
    const float* b2a = (const float*)d_in[10];
    const float* w2b = (const float*)d_in[11];
    const float* b2b = (const float*)d_in[12];
    float* out = (float*)d_out;

    stats1<<<dim3(4, NN), 256>>>(x);
    stats2<<<NCH, 256>>>(g1, b1g, g2, b2g);

    cudaFuncSetAttribute(main_mma, cudaFuncAttributeMaxDynamicSharedMemorySize, SMEM_SZ);
    main_mma<<<dim3(30, NN), THREADS, SMEM_SZ>>>(
        w1a, b1a, w1b, b1b, w2a, b2a, w2b, b2b, out);
}

// round 10
// speedup vs baseline: 3.9949x; 1.4230x over previous
#include <cuda_runtime.h>
#include <cuda_fp16.h>
#include <cstdint>

#define NN   256
#define TT   300
#define NV   25
#define NCH  75
#define NP   (NV * TT)            // 7500
#define MTILE 128                 // points per tile
#define NTPB  60                  // tiles per batch row (60*128 = 7680 >= 7500)
#define NTILES (NN * NTPB)        // 15360
#define THREADS 256
#define GRID_MAIN 296             // 2 CTAs per SM, persistent

// parent joint (0-indexed)
__constant__ int c_par[NV] = {1,20,20,2,20,4,5,6,20,8,9,10,0,12,13,14,0,16,17,18,20,22,7,24,11};

// folded BN affine per channel (index = c*25+v)
__device__ float g_sc1[NCH], g_sh1[NCH], g_sc2[NCH], g_sh2[NCH];

// bone / t_bone scratch: [n][ch 0..5][p]
__device__ float g_bone[(size_t)NN * 6 * NP];

// stats partials
#define SBLK 1024
__device__ float g_ps1[NCH * 3 * SBLK];
__device__ float g_pq1[NCH * 3 * SBLK];
__device__ float g_ps2[NCH * 3 * SBLK];
__device__ float g_pq2[NCH * 3 * SBLK];

__device__ __forceinline__ uint32_t s2u(const void* p) {
    uint32_t a;
    asm("{ .reg .u64 t; cvta.to.shared.u64 t, %1; cvt.u32.u64 %0, t; }" : "=r"(a) : "l"(p));
    return a;
}

__device__ __forceinline__ void ldsm4(uint32_t* r, uint32_t addr) {
    asm volatile("ldmatrix.sync.aligned.m8n8.x4.shared.b16 {%0,%1,%2,%3}, [%4];"
                 : "=r"(r[0]), "=r"(r[1]), "=r"(r[2]), "=r"(r[3]) : "r"(addr));
}

__device__ __forceinline__ void mma16816(float* d, const uint32_t* a, uint32_t b0, uint32_t b1) {
    asm volatile(
        "mma.sync.aligned.m16n8k16.row.col.f32.f16.f16.f32 "
        "{%0,%1,%2,%3}, {%4,%5,%6,%7}, {%8,%9}, {%0,%1,%2,%3};"
        : "+f"(d[0]), "+f"(d[1]), "+f"(d[2]), "+f"(d[3])
        : "r"(a[0]), "r"(a[1]), "r"(a[2]), "r"(a[3]), "r"(b0), "r"(b1));
}

// ---------------------------------------------------------------------------
// stats + bone precompute: grid (4 t-chunks, 256 n), 256 threads
// ---------------------------------------------------------------------------
__global__ __launch_bounds__(256) void stats1(const float* __restrict__ x) {
    __shared__ float rows[76][76];
    int tc = blockIdx.x, n = blockIdx.y;
    int t0 = tc * 75;
    int tid = threadIdx.x;

    for (int i = tid; i < 76 * NCH; i += 256) {
        int r = i / NCH, c = i - r * NCH;
        int t = t0 + r;
        rows[r][c] = (t < TT) ? x[((size_t)n * TT + t) * NCH + c] : 0.0f;
    }
    __syncthreads();

    float* bp = g_bone + (size_t)n * 6 * NP;
    for (int i = tid; i < NCH * 75; i += 256) {
        int ch = i / 75, r = i - ch * 75;
        int c = ch / NV, v = ch - c * NV;
        int ci = v * 3 + c, pi = c_par[v] * 3 + c;
        float b = rows[r][ci] - rows[r][pi];
        float d = 0.0f;
        if (t0 + r < TT - 1) d = (rows[r + 1][ci] - rows[r + 1][pi]) - b;
        size_t pidx = (size_t)v * TT + t0 + r;
        bp[(size_t)c * NP + pidx]       = b;
        bp[(size_t)(3 + c) * NP + pidx] = d;
    }

    int g = tid / NCH;
    int ch = tid - g * NCH;
    if (g < 3) {
        int c = ch / NV, v = ch - c * NV;
        int ci = v * 3 + c, pi = c_par[v] * 3 + c;
        float s1 = 0, q1 = 0, s2 = 0, q2 = 0;
        for (int r = g; r < 75; r += 3) {
            float b = rows[r][ci] - rows[r][pi];
            s1 += b; q1 += b * b;
            if (t0 + r < TT - 1) {
                float d = (rows[r + 1][ci] - rows[r + 1][pi]) - b;
                s2 += d; q2 += d * d;
            }
        }
        int idx = (ch * 3 + g) * SBLK + (tc * NN + n);
        g_ps1[idx] = s1; g_pq1[idx] = q1;
        g_ps2[idx] = s2; g_pq2[idx] = q2;
    }
}

__global__ __launch_bounds__(256) void stats2(
    const float* __restrict__ g1, const float* __restrict__ b1,
    const float* __restrict__ g2, const float* __restrict__ b2)
{
    int ch = blockIdx.x;
    int tid = threadIdx.x;
    float s1 = 0, q1 = 0, s2 = 0, q2 = 0;
    for (int g = 0; g < 3; g++) {
        int base = (ch * 3 + g) * SBLK;
        for (int i = tid; i < SBLK; i += 256) {
            s1 += g_ps1[base + i]; q1 += g_pq1[base + i];
            s2 += g_ps2[base + i]; q2 += g_pq2[base + i];
        }
    }
    __shared__ float red[4][256];
    red[0][tid] = s1; red[1][tid] = q1; red[2][tid] = s2; red[3][tid] = q2;
    __syncthreads();
    for (int s = 128; s > 0; s >>= 1) {
        if (tid < s) {
            #pragma unroll
            for (int j = 0; j < 4; j++) red[j][tid] += red[j][tid + s];
        }
        __syncthreads();
    }
    if (tid == 0) {
        const float inv = 1.0f / (float)(NN * TT);
        float m1 = red[0][0] * inv;
        float v1 = red[1][0] * inv - m1 * m1;
        float sc1 = rsqrtf(v1 + 1e-5f) * g1[ch];
        g_sc1[ch] = sc1;
        g_sh1[ch] = b1[ch] - m1 * sc1;
        float m2 = red[2][0] * inv;
        float v2 = red[3][0] * inv - m2 * m2;
        float sc2 = rsqrtf(v2 + 1e-5f) * g2[ch];
        g_sc2[ch] = sc2;
        g_sh2[ch] = b2[ch] - m2 * sc2;
    }
}

// ---------------------------------------------------------------------------
// main kernel: persistent CTAs; warp tile m32 x (n32 x 2 branches)
// ---------------------------------------------------------------------------
#define ASTR 144                       // A row stride bytes (64 fp16 + pad)
#define BSTR 144                       // B row stride bytes
#define OFF_A1  0
#define OFF_A2  (OFF_A1 + MTILE * ASTR)
#define OFF_B   (OFF_A2 + MTILE * ASTR)
#define OFF_ZS  (OFF_B + 128 * BSTR)   // z/y staging: 128 points x 32 bytes
#define OFF_BB1 (OFF_ZS + MTILE * 32)
#define OFF_BB2 (OFF_BB1 + 256)
#define SMEM_SZ (OFF_BB2 + 256)

extern __shared__ char smem[];

__global__ __launch_bounds__(THREADS, 2) void main_mma(
    const float* __restrict__ w1a, const float* __restrict__ b1a,
    const float* __restrict__ w1b, const float* __restrict__ b1b,
    const float* __restrict__ w2a, const float* __restrict__ b2a,
    const float* __restrict__ w2b, const float* __restrict__ b2b,
    float* __restrict__ out)
{
    const int tid  = threadIdx.x;
    const int wid  = tid >> 5, lane = tid & 31;

    // ---- one-time staging: fused weight tile (fp16) + biases ----
    for (int i = tid; i < 64 * 64; i += THREADS) {
        int o = i >> 6, h = i & 63;
        *(__half*)(smem + OFF_B + o * BSTR + h * 2)        = __float2half_rn(w1b[i]);
        *(__half*)(smem + OFF_B + (o + 64) * BSTR + h * 2) = __float2half_rn(w2b[i]);
    }
    if (tid < 64) {
        ((float*)(smem + OFF_BB1))[tid] = b1b[tid];
    } else if (tid < 128) {
        ((float*)(smem + OFF_BB2))[tid - 64] = b2b[tid - 64];
    }

    // ---- layer-1 weights in registers (thread owns o-pair = lane) ----
    const int o0 = lane * 2, o1 = lane * 2 + 1;
    const float4 wp1 = make_float4(w1a[o0*3], w1a[o0*3+1], w1a[o0*3+2], b1a[o0]);
    const float4 wq1 = make_float4(w1a[o1*3], w1a[o1*3+1], w1a[o1*3+2], b1a[o1]);
    const float4 wp2 = make_float4(w2a[o0*3], w2a[o0*3+1], w2a[o0*3+2], b2a[o0]);
    const float4 wq2 = make_float4(w2a[o1*3], w2a[o1*3+1], w2a[o1*3+2], b2a[o1]);

    const uint32_t sA1 = s2u(smem + OFF_A1), sA2 = s2u(smem + OFF_A2);
    const uint32_t sB  = s2u(smem + OFF_B);

    // MMA warp tiling: pg = point-group (32 pts), oh = o-half (32 outs)
    const int pg = wid & 3, oh = wid >> 2;
    // A frag addr components (x4, m16k16)
    const uint32_t arow = (uint32_t)(pg * 32 + (lane & 15)) * ASTR + (lane >> 4) * 16;
    // B frag addr components (x4 = 8 rows x 4 k-matrices)
    const uint32_t brow1 = (uint32_t)(oh * 32 + (lane & 7)) * BSTR + (lane >> 3) * 16;
    const uint32_t brow2 = brow1 + 64 * BSTR;

    for (int t = blockIdx.x; t < NTILES; t += GRID_MAIN) {
        const int n   = t / NTPB;
        const int tp0 = (t - n * NTPB) * MTILE;
        const float* bnp = g_bone + (size_t)n * 6 * NP;

        __syncthreads();   // staging visible (first iter); A reuse safety (later)

        // ---- z/y prep: one thread per point ----
        if (tid < MTILE) {
            const int pg_  = tp0 + tid;
            const int pgc  = (pg_ < NP) ? pg_ : (NP - 1);
            const int v    = pgc / TT;
            float z0 = g_sc1[v]          * bnp[pgc]          + g_sh1[v];
            float z1 = g_sc1[NV + v]     * bnp[NP + pgc]     + g_sh1[NV + v];
            float z2 = g_sc1[2 * NV + v] * bnp[2 * NP + pgc] + g_sh1[2 * NV + v];
            float y0 = g_sc2[v]          * bnp[3 * NP + pgc] + g_sh2[v];
            float y1 = g_sc2[NV + v]     * bnp[4 * NP + pgc] + g_sh2[NV + v];
            float y2 = g_sc2[2 * NV + v] * bnp[5 * NP + pgc] + g_sh2[2 * NV + v];
            *(float4*)(smem + OFF_ZS + tid * 32)      = make_float4(z0, z1, z2, 0.f);
            *(float4*)(smem + OFF_ZS + tid * 32 + 16) = make_float4(y0, y1, y2, 0.f);
        }
        __syncthreads();

        // ---- H phase: thread = o-pair (lane), 16 points per warp ----
        #pragma unroll
        for (int i = 0; i < 16; i++) {
            const int p = wid * 16 + i;
            float4 z = *(const float4*)(smem + OFF_ZS + p * 32);
            float4 y = *(const float4*)(smem + OFF_ZS + p * 32 + 16);
            float h0 = fmaxf(fmaf(wp1.x, z.x, fmaf(wp1.y, z.y, fmaf(wp1.z, z.z, wp1.w))), 0.0f);
            float h1 = fmaxf(fmaf(wq1.x, z.x, fmaf(wq1.y, z.y, fmaf(wq1.z, z.z, wq1.w))), 0.0f);
            uint32_t pk;
            asm("cvt.rn.f16x2.f32 %0, %1, %2;" : "=r"(pk) : "f"(h1), "f"(h0));
            *(uint32_t*)(smem + OFF_A1 + p * ASTR + lane * 4) = pk;

            float g0 = fmaxf(fmaf(wp2.x, y.x, fmaf(wp2.y, y.y, fmaf(wp2.z, y.z, wp2.w))), 0.0f);
            float g1 = fmaxf(fmaf(wq2.x, y.x, fmaf(wq2.y, y.y, fmaf(wq2.z, y.z, wq2.w))), 0.0f);
            asm("cvt.rn.f16x2.f32 %0, %1, %2;" : "=r"(pk) : "f"(g1), "f"(g0));
            *(uint32_t*)(smem + OFF_A2 + p * ASTR + lane * 4) = pk;
        }
        __syncthreads();

        // ---- MMA phase: warp = m32 x n32 x 2 branches ----
        float a1[2][4][4], a2[2][4][4];
        #pragma unroll
        for (int mt = 0; mt < 2; mt++)
            #pragma unroll
            for (int nt = 0; nt < 4; nt++)
                #pragma unroll
                for (int q = 0; q < 4; q++) { a1[mt][nt][q] = 0.f; a2[mt][nt][q] = 0.f; }

        #pragma unroll
        for (int kcp = 0; kcp < 2; kcp++) {
            uint32_t af[2][2][4];
            // ---- branch 1 ----
            #pragma unroll
            for (int mt = 0; mt < 2; mt++)
                #pragma unroll
                for (int k2 = 0; k2 < 2; k2++)
                    ldsm4(af[mt][k2], sA1 + arow + (uint32_t)mt * 16 * ASTR + (kcp * 2 + k2) * 32);
            #pragma unroll
            for (int nt = 0; nt < 4; nt++) {
                uint32_t bf[4];
                ldsm4(bf, sB + brow1 + (uint32_t)nt * 8 * BSTR + kcp * 64);
                #pragma unroll
                for (int k2 = 0; k2 < 2; k2++)
                    #pragma unroll
                    for (int mt = 0; mt < 2; mt++)
                        mma16816(a1[mt][nt], af[mt][k2], bf[2*k2], bf[2*k2+1]);
            }
            // ---- branch 2 ----
            #pragma unroll
            for (int mt = 0; mt < 2; mt++)
                #pragma unroll
                for (int k2 = 0; k2 < 2; k2++)
                    ldsm4(af[mt][k2], sA2 + arow + (uint32_t)mt * 16 * ASTR + (kcp * 2 + k2) * 32);
            #pragma unroll
            for (int nt = 0; nt < 4; nt++) {
                uint32_t bf[4];
                ldsm4(bf, sB + brow2 + (uint32_t)nt * 8 * BSTR + kcp * 64);
                #pragma unroll
                for (int k2 = 0; k2 < 2; k2++)
                    #pragma unroll
                    for (int mt = 0; mt < 2; mt++)
                        mma16816(a2[mt][nt], af[mt][k2], bf[2*k2], bf[2*k2+1]);
            }
        }

        // ---- epilogue: bias + relu + sum, direct STG ----
        {
            const float* bb1 = (const float*)(smem + OFF_BB1);
            const float* bb2 = (const float*)(smem + OFF_BB2);
            float* ob = out + (size_t)n * 64 * NP;
            #pragma unroll
            for (int mt = 0; mt < 2; mt++) {
                const int r0 = tp0 + pg * 32 + mt * 16 + (lane >> 2);
                #pragma unroll
                for (int nt = 0; nt < 4; nt++) {
                    const int oc = oh * 32 + nt * 8 + (lane & 3) * 2;
                    float u0 = bb1[oc], u1 = bb1[oc + 1];
                    float w0 = bb2[oc], w1 = bb2[oc + 1];
                    if (r0 < NP) {
                        ob[(size_t)oc * NP + r0]       = fmaxf(a1[mt][nt][0] + u0, 0.f) + fmaxf(a2[mt][nt][0] + w0, 0.f);
                        ob[(size_t)(oc + 1) * NP + r0] = fmaxf(a1[mt][nt][1] + u1, 0.f) + fmaxf(a2[mt][nt][1] + w1, 0.f);
                    }
                    if (r0 + 8 < NP) {
                        ob[(size_t)oc * NP + r0 + 8]       = fmaxf(a1[mt][nt][2] + u0, 0.f) + fmaxf(a2[mt][nt][2] + w0, 0.f);
                        ob[(size_t)(oc + 1) * NP + r0 + 8] = fmaxf(a1[mt][nt][3] + u1, 0.f) + fmaxf(a2[mt][nt][3] + w1, 0.f);
                    }
                }
            }
        }
    }
}

// ---------------------------------------------------------------------------
extern "C" void kernel_launch(void* const* d_in, const int* in_sizes, int n_in,
                              void* d_out, int out_size)
{
    const float* x   = (const float*)d_in[0];
    const float* g1  = (const float*)d_in[1];
    const float* b1g = (const float*)d_in[2];
    const float* w1a = (const float*)d_in[3];
    const float* b1a = (const float*)d_in[4];
    const float* w1b = (const float*)d_in[5];
    const float* b1b = (const float*)d_in[6];
    const float* g2  = (const float*)d_in[7];
    const float* b2g = (const float*)d_in[8];
    const float* w2a = (const float*)d_in[9];
    const float* b2a = (const float*)d_in[10];
    const float* w2b = (const float*)d_in[11];
    const float* b2b = (const float*)d_in[12];
    float* out = (float*)d_out;

    stats1<<<dim3(4, NN), 256>>>(x);
    stats2<<<NCH, 256>>>(g1, b1g, g2, b2g);

    cudaFuncSetAttribute(main_mma, cudaFuncAttributeMaxDynamicSharedMemorySize, SMEM_SZ);
    main_mma<<<GRID_MAIN, THREADS, SMEM_SZ>>>(
        w1a, b1a, w1b, b1b, w2a, b2a, w2b, b2b, out);
}